// round 1
// baseline (speedup 1.0000x reference)
#include <cuda_runtime.h>

// Problem constants (shapes are fixed by the dataset).
#define CHN 128

// Scratch (no allocations allowed): degree/dis and aggregated h.
static __device__ float g_deg[100000];
static __device__ float g_h[(size_t)100000 * CHN];

// ---------------------------------------------------------------------------
// Packed f32x2 helpers (FFMA2 path — only reachable via PTX fma.rn.f32x2)
// ---------------------------------------------------------------------------
#define PACK2(o, a, b) \
    asm("mov.b64 %0, {%1, %2};" : "=l"(o) : "r"(__float_as_uint(a)), "r"(__float_as_uint(b)))
#define PACK_DUP(o, f) \
    asm("mov.b64 %0, {%1, %1};" : "=l"(o) : "r"(__float_as_uint(f)))
#define FMA2(acc, a, b) \
    asm("fma.rn.f32x2 %0, %1, %2, %0;" : "+l"(acc) : "l"(a), "l"(b))
#define UNPACK2(lo, hi, v) do { unsigned _l, _h; \
    asm("mov.b64 {%0, %1}, %2;" : "=r"(_l), "=r"(_h) : "l"(v)); \
    lo = __uint_as_float(_l); hi = __uint_as_float(_h); } while (0)

// ---------------------------------------------------------------------------
// Stage 1: degree (with self loop) -> dis = rsqrt(deg)
// ---------------------------------------------------------------------------
__global__ void k_init_deg(int n) {
    int i = blockIdx.x * blockDim.x + threadIdx.x;
    if (i < n) g_deg[i] = 1.0f;  // self loop contributes 1
}

__global__ void k_edge_deg(const int* __restrict__ dst, int e) {
    int i = blockIdx.x * blockDim.x + threadIdx.x;
    if (i < e) atomicAdd(&g_deg[dst[i]], 1.0f);
}

__global__ void k_rsqrt(int n) {
    int i = blockIdx.x * blockDim.x + threadIdx.x;
    if (i < n) g_deg[i] = rsqrtf(g_deg[i]);
}

// ---------------------------------------------------------------------------
// Stage 2a: h init with self-loop term  h[i] = dis[i]^2 * x[i]
// ---------------------------------------------------------------------------
__global__ void k_hinit(const float4* __restrict__ x4, int n32) {
    int t = blockIdx.x * blockDim.x + threadIdx.x;
    if (t >= n32) return;
    float d = g_deg[t >> 5];
    float d2 = d * d;
    float4 v = x4[t];
    v.x *= d2; v.y *= d2; v.z *= d2; v.w *= d2;
    reinterpret_cast<float4*>(g_h)[t] = v;
}

// ---------------------------------------------------------------------------
// Stage 2b: edge scatter  h[dst] += dis[src]*dis[dst]*x[src]
// One warp per edge; lane covers 4 channels; vector red (no return) to L2.
// ---------------------------------------------------------------------------
__global__ void __launch_bounds__(256) k_spmm(const float4* __restrict__ x4,
                                              const int* __restrict__ src,
                                              const int* __restrict__ dst, int e) {
    int w = (blockIdx.x * 256 + threadIdx.x) >> 5;
    int lane = threadIdx.x & 31;
    if (w >= e) return;
    int s = src[w], d = dst[w];
    float nrm = g_deg[s] * g_deg[d];
    float4 v = x4[(size_t)s * (CHN / 4) + lane];
    float* p = &g_h[(size_t)d * CHN + lane * 4];
    asm volatile("red.global.add.v4.f32 [%0], {%1, %2, %3, %4};"
                 :: "l"(p), "f"(v.x * nrm), "f"(v.y * nrm),
                    "f"(v.z * nrm), "f"(v.w * nrm)
                 : "memory");
}

// ---------------------------------------------------------------------------
// Stage 3: fused  out = relu(c1*h + c2*x0 + beta*([h|x0] @ [W1;W2]))
// Block = 256 threads, 32 rows x 128 cols output tile.
// smem: A[32][256] (g rows then x0 rows, also reused by epilogue)
//       W-chunk[32][128], K looped in 8 chunks of 32. Total 48 KB exactly.
// Thread (warp w, lane l): rows w*4..w*4+3, cols l*4..l*4+3, f32x2 accum.
// ---------------------------------------------------------------------------
__global__ void __launch_bounds__(256) k_gemm(const float* __restrict__ x0,
                                              const float* __restrict__ w1,
                                              const float* __restrict__ w2,
                                              float* __restrict__ out, int n) {
    extern __shared__ float sm[];
    float* As = sm;               // [32][256]
    float* Ws = sm + 32 * 256;    // [32][128]
    const int tid = threadIdx.x;
    const int row0 = blockIdx.x * 32;

    // Load A tile: k<128 -> h (already has self loop + edges), k>=128 -> x0.
    for (int idx = tid; idx < 32 * 64; idx += 256) {
        int r = idx >> 6, q = idx & 63;
        int gr = row0 + r;
        float4 v = make_float4(0.f, 0.f, 0.f, 0.f);
        if (gr < n) {
            if (q < 32) v = reinterpret_cast<const float4*>(g_h + (size_t)gr * CHN)[q];
            else        v = reinterpret_cast<const float4*>(x0 + (size_t)gr * CHN)[q - 32];
        }
        *reinterpret_cast<float4*>(&As[r * 256 + q * 4]) = v;
    }

    const int warp = tid >> 5, lane = tid & 31;
    unsigned long long acc[4][2];
#pragma unroll
    for (int i = 0; i < 4; i++) { acc[i][0] = 0ull; acc[i][1] = 0ull; }

    for (int kc = 0; kc < 8; kc++) {
        __syncthreads();   // A ready (iter 0) / Ws consumed (iters > 0)
        // Load W chunk: rows kc*32..kc*32+31 of [W1;W2].
        for (int idx = tid; idx < 32 * 32; idx += 256) {
            int kk = idx >> 5, q = idx & 31;
            int k = kc * 32 + kk;
            float4 v = (k < 128)
                ? reinterpret_cast<const float4*>(w1 + (size_t)k * CHN)[q]
                : reinterpret_cast<const float4*>(w2 + (size_t)(k - 128) * CHN)[q];
            *reinterpret_cast<float4*>(&Ws[kk * 128 + q * 4]) = v;
        }
        __syncthreads();
#pragma unroll
        for (int kk = 0; kk < 32; kk++) {
            float4 wv = *reinterpret_cast<const float4*>(&Ws[kk * 128 + lane * 4]);
            unsigned long long wp0, wp1;
            PACK2(wp0, wv.x, wv.y);
            PACK2(wp1, wv.z, wv.w);
#pragma unroll
            for (int i = 0; i < 4; i++) {
                float a = As[(warp * 4 + i) * 256 + kc * 32 + kk];  // broadcast LDS
                unsigned long long pa;
                PACK_DUP(pa, a);
                FMA2(acc[i][0], pa, wp0);
                FMA2(acc[i][1], pa, wp1);
            }
        }
    }

    // Epilogue. c1 = (1-alpha)(1-beta) == alpha*(1-beta) = c2 (alpha=0.5).
    const float C1 = 0.15342640972002733f;
    const float BETA = 0.6931471805599453f;
#pragma unroll
    for (int i = 0; i < 4; i++) {
        int r = warp * 4 + i;
        int gr = row0 + r;
        if (gr >= n) continue;
        float4 g = *reinterpret_cast<const float4*>(&As[r * 256 + lane * 4]);
        float4 z = *reinterpret_cast<const float4*>(&As[r * 256 + 128 + lane * 4]);
        float a0, a1, a2, a3;
        UNPACK2(a0, a1, acc[i][0]);
        UNPACK2(a2, a3, acc[i][1]);
        float4 o;
        o.x = fmaxf(C1 * (g.x + z.x) + BETA * a0, 0.f);
        o.y = fmaxf(C1 * (g.y + z.y) + BETA * a1, 0.f);
        o.z = fmaxf(C1 * (g.z + z.z) + BETA * a2, 0.f);
        o.w = fmaxf(C1 * (g.w + z.w) + BETA * a3, 0.f);
        *reinterpret_cast<float4*>(&out[(size_t)gr * CHN + lane * 4]) = o;
    }
}

// ---------------------------------------------------------------------------
// kernel_launch: graph-capturable sequence, no allocs, no syncs.
// Input order (metadata): x, x_0, weight1, weight2, edge_index.
// ---------------------------------------------------------------------------
extern "C" void kernel_launch(void* const* d_in, const int* in_sizes, int n_in,
                              void* d_out, int out_size) {
    const float* x  = (const float*)d_in[0];
    const float* x0 = (const float*)d_in[1];
    const float* w1 = (const float*)d_in[2];
    const float* w2 = (const float*)d_in[3];
    const int*   ei = (const int*)d_in[4];
    float* out = (float*)d_out;

    const int n = in_sizes[0] / CHN;      // 100000
    const int e = in_sizes[4] / 2;        // 800000
    const int* src = ei;
    const int* dst = ei + e;

    k_init_deg<<<(n + 255) / 256, 256>>>(n);
    k_edge_deg<<<(e + 255) / 256, 256>>>(dst, e);
    k_rsqrt<<<(n + 255) / 256, 256>>>(n);

    const int n32 = n * (CHN / 4) / 1;    // n * 32 float4 elements... (n*CHN/4)
    k_hinit<<<((n * 32) + 255) / 256, 256>>>((const float4*)x, n * 32);
    (void)n32;

    k_spmm<<<(e + 7) / 8, 256>>>((const float4*)x, src, dst, e);

    k_gemm<<<(n + 31) / 32, 256, 48 * 1024>>>(x0, w1, w2, out, n);
}

// round 3
// speedup vs baseline: 1.5033x; 1.5033x over previous
#include <cuda_runtime.h>

#define CHN 128
#define NMAX 100000
#define EMAX 800000

// Scratch (static device globals; no allocation allowed).
static __device__ float g_deg[NMAX];                 // degree -> rsqrt(degree)
static __device__ float g_h[(size_t)NMAX * CHN];     // aggregated features
static __device__ int   g_rowptr[NMAX];              // CSR row starts (exclusive scan)
static __device__ int   g_cursor[NMAX];              // scatter cursors -> per-row counts
static __device__ int   g_csrsrc[EMAX];              // CSR column (src) indices
static __device__ int   g_aux[128];                  // scan block sums

__device__ __forceinline__ unsigned cvt_tf32(float f) {
    unsigned r;
    asm("cvt.rna.tf32.f32 %0, %1;" : "=r"(r) : "f"(f));
    return r;
}

// ---------------------------------------------------------------------------
// Stage 1: degree histogram (float; exact for small counts)
// ---------------------------------------------------------------------------
__global__ void k_init(int n) {
    int i = blockIdx.x * blockDim.x + threadIdx.x;
    if (i < n) g_deg[i] = 1.0f;  // self loop
}

__global__ void k_edge_deg(const int* __restrict__ dst, int e) {
    int i = blockIdx.x * blockDim.x + threadIdx.x;
    if (i < e) atomicAdd(&g_deg[dst[i]], 1.0f);
}

// ---------------------------------------------------------------------------
// Stage 2: exclusive scan of edge counts (deg-1) -> rowptr.  3-kernel scan.
// ---------------------------------------------------------------------------
__global__ void __launch_bounds__(1024) k_scan1(int n) {
    __shared__ int wsum[32];
    int i = blockIdx.x * 1024 + threadIdx.x;
    int v = (i < n) ? ((int)g_deg[i] - 1) : 0;
    int x = v;
#pragma unroll
    for (int o = 1; o < 32; o <<= 1) {
        int y = __shfl_up_sync(~0u, x, o);
        if ((threadIdx.x & 31) >= o) x += y;
    }
    if ((threadIdx.x & 31) == 31) wsum[threadIdx.x >> 5] = x;
    __syncthreads();
    if (threadIdx.x < 32) {
        int s = wsum[threadIdx.x];
#pragma unroll
        for (int o = 1; o < 32; o <<= 1) {
            int y = __shfl_up_sync(~0u, s, o);
            if (threadIdx.x >= o) s += y;
        }
        wsum[threadIdx.x] = s;
    }
    __syncthreads();
    int base = (threadIdx.x >= 32) ? wsum[(threadIdx.x >> 5) - 1] : 0;
    if (i < n) g_rowptr[i] = base + x - v;
    if (threadIdx.x == 1023) g_aux[blockIdx.x] = base + x;
}

__global__ void k_scan2(int nb) {
    __shared__ int s[128];
    if (threadIdx.x < nb) s[threadIdx.x] = g_aux[threadIdx.x];
    __syncthreads();
    if (threadIdx.x == 0) {
        int run = 0;
        for (int j = 0; j < nb; j++) { int t = s[j]; s[j] = run; run += t; }
    }
    __syncthreads();
    if (threadIdx.x < nb) g_aux[threadIdx.x] = s[threadIdx.x];
}

__global__ void k_scan3(int n) {
    int i = blockIdx.x * blockDim.x + threadIdx.x;
    if (i < n) {
        g_rowptr[i] += g_aux[i >> 10];
        g_cursor[i] = 0;
    }
}

// ---------------------------------------------------------------------------
// Stage 3: scatter edges into CSR; dis = rsqrt(deg)
// ---------------------------------------------------------------------------
__global__ void k_scatter(const int* __restrict__ src, const int* __restrict__ dst, int e) {
    int i = blockIdx.x * blockDim.x + threadIdx.x;
    if (i >= e) return;
    int d = dst[i];
    int pos = g_rowptr[d] + atomicAdd(&g_cursor[d], 1);
    g_csrsrc[pos] = src[i];
}

__global__ void k_rsqrt(int n) {
    int i = blockIdx.x * blockDim.x + threadIdx.x;
    if (i < n) g_deg[i] = rsqrtf(g_deg[i]);
}

// ---------------------------------------------------------------------------
// Stage 4: CSR SpMM — one warp per dst row, no atomics.
// h[d] = dis[d]^2 * x[d] + sum_e dis[d]*dis[src] * x[src]
// ---------------------------------------------------------------------------
__global__ void __launch_bounds__(256) k_spmm(const float4* __restrict__ x4, int n) {
    int w = (blockIdx.x * 256 + threadIdx.x) >> 5;
    int lane = threadIdx.x & 31;
    if (w >= n) return;
    float dd = g_deg[w];
    float4 acc = x4[(size_t)w * 32 + lane];
    float c = dd * dd;
    acc.x *= c; acc.y *= c; acc.z *= c; acc.w *= c;
    int beg = g_rowptr[w];
    int cnt = g_cursor[w];
    for (int c0 = 0; c0 < cnt; c0 += 32) {
        int m = min(32, cnt - c0);
        int s = 0;
        float wv = 0.f;
        if (lane < m) {
            s = g_csrsrc[beg + c0 + lane];
            wv = g_deg[s] * dd;
        }
        for (int j = 0; j < m; j++) {
            int sj = __shfl_sync(~0u, s, j);
            float nr = __shfl_sync(~0u, wv, j);
            float4 v = x4[(size_t)sj * 32 + lane];
            acc.x += nr * v.x; acc.y += nr * v.y;
            acc.z += nr * v.z; acc.w += nr * v.w;
        }
    }
    reinterpret_cast<float4*>(g_h)[(size_t)w * 32 + lane] = acc;
}

// ---------------------------------------------------------------------------
// Stage 5: out = relu([h|x0] @ (beta*[W1;W2] + c1*[I;I]))   via tf32 mma.sync
// Block: 256 thr (8 warps), tile 128 rows x 128 cols, K=256 in 8 chunks of 32.
// smem: As[128][36], Ws[32][136] — both fragment-load patterns conflict-free:
//   A: bank = (g*36 + t4)    mod 32 = g*4 + t4  (32 distinct)
//   B: bank = (t4*136 + g)   mod 32 = t4*8 + g  (32 distinct)
// ---------------------------------------------------------------------------
#define SA 36
#define SB 136

__global__ void __launch_bounds__(256) k_gemm(const float* __restrict__ x0,
                                              const float* __restrict__ w1,
                                              const float* __restrict__ w2,
                                              float* __restrict__ out, int n) {
    __shared__ unsigned As[128 * SA];
    __shared__ unsigned Ws[32 * SB];
    const float BETA = 0.6931471805599453f;
    const float C1 = 0.15342640972002733f;

    int tid = threadIdx.x, warp = tid >> 5, lane = tid & 31;
    int g = lane >> 2, t4 = lane & 3;
    int row0 = blockIdx.x * 128;

    float acc[16][4];
#pragma unroll
    for (int nt = 0; nt < 16; nt++)
#pragma unroll
        for (int j = 0; j < 4; j++) acc[nt][j] = 0.f;

    for (int kc = 0; kc < 8; kc++) {
        __syncthreads();
        // A chunk: rows row0..+128, K-cols kc*32..+32   (k<128 -> h, else x0)
        const float* Asrc = (kc < 4) ? g_h : x0;
        int kbase = (kc & 3) * 32;
        for (int t = tid; t < 128 * 8; t += 256) {
            int r = t >> 3, q = t & 7;
            int gr = row0 + r;
            float4 v = make_float4(0.f, 0.f, 0.f, 0.f);
            if (gr < n) v = *(const float4*)(Asrc + (size_t)gr * CHN + kbase + q * 4);
            uint4 u = make_uint4(cvt_tf32(v.x), cvt_tf32(v.y), cvt_tf32(v.z), cvt_tf32(v.w));
            *reinterpret_cast<uint4*>(&As[r * SA + q * 4]) = u;
        }
        // W chunk with folded epilogue diagonal: beta*W[kg][c] + c1*(kg%128==c)
        for (int t = tid; t < 32 * 32; t += 256) {
            int kk = t >> 5, q = t & 31;
            int kg = kc * 32 + kk;
            const float* Wr = (kg < 128) ? (w1 + (size_t)kg * CHN)
                                         : (w2 + (size_t)(kg - 128) * CHN);
            float4 v = *(const float4*)(Wr + q * 4);
            int c = q * 4, kd = kg & 127;
            uint4 u;
            u.x = cvt_tf32(BETA * v.x + (kd == c + 0 ? C1 : 0.f));
            u.y = cvt_tf32(BETA * v.y + (kd == c + 1 ? C1 : 0.f));
            u.z = cvt_tf32(BETA * v.z + (kd == c + 2 ? C1 : 0.f));
            u.w = cvt_tf32(BETA * v.w + (kd == c + 3 ? C1 : 0.f));
            *reinterpret_cast<uint4*>(&Ws[kk * SB + c]) = u;
        }
        __syncthreads();

#pragma unroll
        for (int k8 = 0; k8 < 4; k8++) {
            int ar = warp * 16 + g;
            int kb = k8 * 8;
            unsigned a0 = As[ar * SA + kb + t4];
            unsigned a1 = As[(ar + 8) * SA + kb + t4];
            unsigned a2 = As[ar * SA + kb + t4 + 4];
            unsigned a3 = As[(ar + 8) * SA + kb + t4 + 4];
#pragma unroll
            for (int nt = 0; nt < 16; nt++) {
                unsigned b0 = Ws[(kb + t4) * SB + nt * 8 + g];
                unsigned b1 = Ws[(kb + t4 + 4) * SB + nt * 8 + g];
                asm volatile(
                    "mma.sync.aligned.m16n8k8.row.col.f32.tf32.tf32.f32 "
                    "{%0,%1,%2,%3}, {%4,%5,%6,%7}, {%8,%9}, {%0,%1,%2,%3};"
                    : "+f"(acc[nt][0]), "+f"(acc[nt][1]),
                      "+f"(acc[nt][2]), "+f"(acc[nt][3])
                    : "r"(a0), "r"(a1), "r"(a2), "r"(a3), "r"(b0), "r"(b1));
            }
        }
    }

    // Epilogue is just relu (folded into W).  c0/c1: row g, cols 2*t4, 2*t4+1;
    // c2/c3: row g+8, same cols.
    int r1 = row0 + warp * 16 + g;
    int r2 = r1 + 8;
#pragma unroll
    for (int nt = 0; nt < 16; nt++) {
        int c = nt * 8 + t4 * 2;
        if (r1 < n) {
            float2 o = make_float2(fmaxf(acc[nt][0], 0.f), fmaxf(acc[nt][1], 0.f));
            *reinterpret_cast<float2*>(out + (size_t)r1 * CHN + c) = o;
        }
        if (r2 < n) {
            float2 o = make_float2(fmaxf(acc[nt][2], 0.f), fmaxf(acc[nt][3], 0.f));
            *reinterpret_cast<float2*>(out + (size_t)r2 * CHN + c) = o;
        }
    }
}

// ---------------------------------------------------------------------------
extern "C" void kernel_launch(void* const* d_in, const int* in_sizes, int n_in,
                              void* d_out, int out_size) {
    const float* x  = (const float*)d_in[0];
    const float* x0 = (const float*)d_in[1];
    const float* w1 = (const float*)d_in[2];
    const float* w2 = (const float*)d_in[3];
    const int*   ei = (const int*)d_in[4];
    float* out = (float*)d_out;

    const int n = in_sizes[0] / CHN;   // 100000
    const int e = in_sizes[4] / 2;     // 800000
    const int* src = ei;
    const int* dst = ei + e;
    const int nb = (n + 1023) / 1024;

    k_init<<<(n + 255) / 256, 256>>>(n);
    k_edge_deg<<<(e + 255) / 256, 256>>>(dst, e);
    k_scan1<<<nb, 1024>>>(n);
    k_scan2<<<1, 128>>>(nb);
    k_scan3<<<(n + 255) / 256, 256>>>(n);
    k_scatter<<<(e + 255) / 256, 256>>>(src, dst, e);
    k_rsqrt<<<(n + 255) / 256, 256>>>(n);
    k_spmm<<<(n + 7) / 8, 256>>>((const float4*)x, n);
    k_gemm<<<(n + 127) / 128, 256>>>(x0, w1, w2, out, n);
}

// round 5
// speedup vs baseline: 1.9269x; 1.2818x over previous
#include <cuda_runtime.h>

#define CHN 128
#define NMAX 100000
#define EMAX 800000

static __device__ float g_deg[NMAX];                 // degree -> rsqrt(degree)
static __device__ float g_h[(size_t)NMAX * CHN];     // aggregated features
static __device__ int   g_rowptr[NMAX];              // CSR row starts
static __device__ int   g_cursor[NMAX];              // scatter cursors -> counts
static __device__ int   g_csrsrc[EMAX];              // CSR column (src) indices
static __device__ int   g_aux[128];                  // scan block sums

__device__ __forceinline__ unsigned cvt_tf32(float f) {
    unsigned r;
    asm("cvt.rna.tf32.f32 %0, %1;" : "=r"(r) : "f"(f));
    return r;
}

// ---------------------------------------------------------------------------
// Stage 1: degree histogram
// ---------------------------------------------------------------------------
__global__ void k_init(int n) {
    int i = blockIdx.x * blockDim.x + threadIdx.x;
    if (i < n) g_deg[i] = 1.0f;  // self loop
}

__global__ void k_edge_deg(const int* __restrict__ dst, int e) {
    int i = blockIdx.x * blockDim.x + threadIdx.x;
    if (i < e) atomicAdd(&g_deg[dst[i]], 1.0f);
}

// ---------------------------------------------------------------------------
// Stage 2: exclusive scan of (deg-1) -> rowptr; fused dis = rsqrt(deg)
// ---------------------------------------------------------------------------
__global__ void __launch_bounds__(1024) k_scan1(int n) {
    __shared__ int wsum[32];
    int i = blockIdx.x * 1024 + threadIdx.x;
    float dg = (i < n) ? g_deg[i] : 1.0f;
    int v = (i < n) ? ((int)dg - 1) : 0;
    if (i < n) g_deg[i] = rsqrtf(dg);      // fuse rsqrt here (deg final)
    int x = v;
#pragma unroll
    for (int o = 1; o < 32; o <<= 1) {
        int y = __shfl_up_sync(~0u, x, o);
        if ((threadIdx.x & 31) >= o) x += y;
    }
    if ((threadIdx.x & 31) == 31) wsum[threadIdx.x >> 5] = x;
    __syncthreads();
    if (threadIdx.x < 32) {
        int s = wsum[threadIdx.x];
#pragma unroll
        for (int o = 1; o < 32; o <<= 1) {
            int y = __shfl_up_sync(~0u, s, o);
            if (threadIdx.x >= o) s += y;
        }
        wsum[threadIdx.x] = s;
    }
    __syncthreads();
    int base = (threadIdx.x >= 32) ? wsum[(threadIdx.x >> 5) - 1] : 0;
    if (i < n) g_rowptr[i] = base + x - v;
    if (threadIdx.x == 1023) g_aux[blockIdx.x] = base + x;
}

__global__ void k_scan2(int nb) {   // nb <= 128; shfl scan over 128 threads
    int tid = threadIdx.x;
    int v = (tid < nb) ? g_aux[tid] : 0;
    int x = v;
#pragma unroll
    for (int o = 1; o < 32; o <<= 1) {
        int y = __shfl_up_sync(~0u, x, o);
        if ((tid & 31) >= o) x += y;
    }
    __shared__ int ws[4];
    if ((tid & 31) == 31) ws[tid >> 5] = x;
    __syncthreads();
    if (tid < 4) {
        int s = ws[tid];
        int r0 = __shfl_up_sync(0xF, s, 1); if (tid >= 1) s += r0;
        int r1 = __shfl_up_sync(0xF, s, 2); if (tid >= 2) s += r1;
        ws[tid] = s;
    }
    __syncthreads();
    int base = (tid >= 32) ? ws[(tid >> 5) - 1] : 0;
    if (tid < nb) g_aux[tid] = base + x - v;   // exclusive
}

__global__ void k_scan3(int n) {
    int i = blockIdx.x * blockDim.x + threadIdx.x;
    if (i < n) {
        g_rowptr[i] += g_aux[i >> 10];
        g_cursor[i] = 0;
    }
}

// ---------------------------------------------------------------------------
// Stage 3: scatter edges into CSR
// ---------------------------------------------------------------------------
__global__ void k_scatter(const int* __restrict__ src, const int* __restrict__ dst, int e) {
    int i = blockIdx.x * blockDim.x + threadIdx.x;
    if (i >= e) return;
    int d = dst[i];
    int pos = g_rowptr[d] + atomicAdd(&g_cursor[d], 1);
    g_csrsrc[pos] = src[i];
}

// ---------------------------------------------------------------------------
// Stage 4: CSR SpMM — one warp per dst row; gathers batched x4 for MLP.
// ---------------------------------------------------------------------------
__global__ void __launch_bounds__(256) k_spmm(const float4* __restrict__ x4, int n) {
    int w = (blockIdx.x * 256 + threadIdx.x) >> 5;
    int lane = threadIdx.x & 31;
    if (w >= n) return;
    float dd = g_deg[w];
    float4 acc = x4[(size_t)w * 32 + lane];
    float c = dd * dd;
    acc.x *= c; acc.y *= c; acc.z *= c; acc.w *= c;
    int beg = g_rowptr[w];
    int cnt = g_cursor[w];
    for (int c0 = 0; c0 < cnt; c0 += 32) {
        int m = min(32, cnt - c0);
        int s = 0;
        float wv = 0.f;
        if (lane < m) {
            s = g_csrsrc[beg + c0 + lane];
            wv = g_deg[s] * dd;
        }
        int j = 0;
        for (; j + 4 <= m; j += 4) {
            int s0 = __shfl_sync(~0u, s, j);
            int s1 = __shfl_sync(~0u, s, j + 1);
            int s2 = __shfl_sync(~0u, s, j + 2);
            int s3 = __shfl_sync(~0u, s, j + 3);
            float n0 = __shfl_sync(~0u, wv, j);
            float n1 = __shfl_sync(~0u, wv, j + 1);
            float n2 = __shfl_sync(~0u, wv, j + 2);
            float n3 = __shfl_sync(~0u, wv, j + 3);
            float4 v0 = x4[(size_t)s0 * 32 + lane];
            float4 v1 = x4[(size_t)s1 * 32 + lane];
            float4 v2 = x4[(size_t)s2 * 32 + lane];
            float4 v3 = x4[(size_t)s3 * 32 + lane];
            acc.x += n0 * v0.x; acc.y += n0 * v0.y; acc.z += n0 * v0.z; acc.w += n0 * v0.w;
            acc.x += n1 * v1.x; acc.y += n1 * v1.y; acc.z += n1 * v1.z; acc.w += n1 * v1.w;
            acc.x += n2 * v2.x; acc.y += n2 * v2.y; acc.z += n2 * v2.z; acc.w += n2 * v2.w;
            acc.x += n3 * v3.x; acc.y += n3 * v3.y; acc.z += n3 * v3.z; acc.w += n3 * v3.w;
        }
        for (; j < m; j++) {
            int sj = __shfl_sync(~0u, s, j);
            float nr = __shfl_sync(~0u, wv, j);
            float4 v = x4[(size_t)sj * 32 + lane];
            acc.x += nr * v.x; acc.y += nr * v.y;
            acc.z += nr * v.z; acc.w += nr * v.w;
        }
    }
    reinterpret_cast<float4*>(g_h)[(size_t)w * 32 + lane] = acc;
}

// ---------------------------------------------------------------------------
// Stage 5: out = relu([h|x0] @ (beta*[W1;W2] + c1*[I;I]))  via tf32 mma.sync
// Register double-buffered K-chunks: LDG for kc+1 overlaps mma of kc.
// smem: As[128][36], Ws[32][136] — both fragment patterns conflict-free.
// ---------------------------------------------------------------------------
#define SA 36
#define SB 136

__global__ void __launch_bounds__(256) k_gemm(const float* __restrict__ x0,
                                              const float* __restrict__ w1,
                                              const float* __restrict__ w2,
                                              float* __restrict__ out, int n) {
    __shared__ unsigned As[128 * SA];
    __shared__ unsigned Ws[32 * SB];
    const float BETA = 0.6931471805599453f;
    const float C1 = 0.15342640972002733f;

    int tid = threadIdx.x, warp = tid >> 5, lane = tid & 31;
    int g = lane >> 2, t4 = lane & 3;
    int row0 = blockIdx.x * 128;

    float4 ra[4];   // A-chunk staging (128x32 / 256 thr = 4 float4)
    float4 rw[4];   // W-chunk staging (32x128 / 256 thr = 4 float4)

    auto loadA = [&](int kc) {
        const float* Asrc = (kc < 4) ? g_h : x0;
        int kbase = (kc & 3) * 32;
#pragma unroll
        for (int i = 0; i < 4; i++) {
            int t = tid + i * 256;
            int r = t >> 3, q = t & 7;
            int gr = row0 + r;
            ra[i] = (gr < n) ? *(const float4*)(Asrc + (size_t)gr * CHN + kbase + q * 4)
                             : make_float4(0.f, 0.f, 0.f, 0.f);
        }
    };
    auto loadW = [&](int kc) {
#pragma unroll
        for (int i = 0; i < 4; i++) {
            int t = tid + i * 256;
            int kk = t >> 5, q = t & 31;
            int kg = kc * 32 + kk;
            const float* Wr = (kg < 128) ? (w1 + (size_t)kg * CHN)
                                         : (w2 + (size_t)(kg - 128) * CHN);
            rw[i] = *(const float4*)(Wr + q * 4);
        }
    };

    float acc[16][4];
#pragma unroll
    for (int nt = 0; nt < 16; nt++)
#pragma unroll
        for (int j = 0; j < 4; j++) acc[nt][j] = 0.f;

    loadA(0);
    loadW(0);

    for (int kc = 0; kc < 8; kc++) {
        __syncthreads();   // smem free (prior mma done)
        // Store staged chunk (tf32 convert + epilogue-diag fold for W)
#pragma unroll
        for (int i = 0; i < 4; i++) {
            int t = tid + i * 256;
            int r = t >> 3, q = t & 7;
            uint4 u = make_uint4(cvt_tf32(ra[i].x), cvt_tf32(ra[i].y),
                                 cvt_tf32(ra[i].z), cvt_tf32(ra[i].w));
            *reinterpret_cast<uint4*>(&As[r * SA + q * 4]) = u;
        }
#pragma unroll
        for (int i = 0; i < 4; i++) {
            int t = tid + i * 256;
            int kk = t >> 5, q = t & 31;
            int kg = kc * 32 + kk, kd = kg & 127, c = q * 4;
            uint4 u;
            u.x = cvt_tf32(BETA * rw[i].x + (kd == c + 0 ? C1 : 0.f));
            u.y = cvt_tf32(BETA * rw[i].y + (kd == c + 1 ? C1 : 0.f));
            u.z = cvt_tf32(BETA * rw[i].z + (kd == c + 2 ? C1 : 0.f));
            u.w = cvt_tf32(BETA * rw[i].w + (kd == c + 3 ? C1 : 0.f));
            *reinterpret_cast<uint4*>(&Ws[kk * SB + c]) = u;
        }
        __syncthreads();
        if (kc < 7) { loadA(kc + 1); loadW(kc + 1); }   // overlap with mma below

#pragma unroll
        for (int k8 = 0; k8 < 4; k8++) {
            int ar = warp * 16 + g;
            int kb = k8 * 8;
            unsigned a0 = As[ar * SA + kb + t4];
            unsigned a1 = As[(ar + 8) * SA + kb + t4];
            unsigned a2 = As[ar * SA + kb + t4 + 4];
            unsigned a3 = As[(ar + 8) * SA + kb + t4 + 4];
#pragma unroll
            for (int nt = 0; nt < 16; nt++) {
                unsigned b0 = Ws[(kb + t4) * SB + nt * 8 + g];
                unsigned b1 = Ws[(kb + t4 + 4) * SB + nt * 8 + g];
                asm volatile(
                    "mma.sync.aligned.m16n8k8.row.col.f32.tf32.tf32.f32 "
                    "{%0,%1,%2,%3}, {%4,%5,%6,%7}, {%8,%9}, {%0,%1,%2,%3};"
                    : "+f"(acc[nt][0]), "+f"(acc[nt][1]),
                      "+f"(acc[nt][2]), "+f"(acc[nt][3])
                    : "r"(a0), "r"(a1), "r"(a2), "r"(a3), "r"(b0), "r"(b1));
            }
        }
    }

    int r1 = row0 + warp * 16 + g;
    int r2 = r1 + 8;
#pragma unroll
    for (int nt = 0; nt < 16; nt++) {
        int c = nt * 8 + t4 * 2;
        if (r1 < n) {
            float2 o = make_float2(fmaxf(acc[nt][0], 0.f), fmaxf(acc[nt][1], 0.f));
            *reinterpret_cast<float2*>(out + (size_t)r1 * CHN + c) = o;
        }
        if (r2 < n) {
            float2 o = make_float2(fmaxf(acc[nt][2], 0.f), fmaxf(acc[nt][3], 0.f));
            *reinterpret_cast<float2*>(out + (size_t)r2 * CHN + c) = o;
        }
    }
}

// ---------------------------------------------------------------------------
extern "C" void kernel_launch(void* const* d_in, const int* in_sizes, int n_in,
                              void* d_out, int out_size) {
    const float* x  = (const float*)d_in[0];
    const float* x0 = (const float*)d_in[1];
    const float* w1 = (const float*)d_in[2];
    const float* w2 = (const float*)d_in[3];
    const int*   ei = (const int*)d_in[4];
    float* out = (float*)d_out;

    const int n = in_sizes[0] / CHN;   // 100000
    const int e = in_sizes[4] / 2;     // 800000
    const int* src = ei;
    const int* dst = ei + e;
    const int nb = (n + 1023) / 1024;

    k_init<<<(n + 255) / 256, 256>>>(n);
    k_edge_deg<<<(e + 255) / 256, 256>>>(dst, e);
    k_scan1<<<nb, 1024>>>(n);
    k_scan2<<<1, 128>>>(nb);
    k_scan3<<<(n + 255) / 256, 256>>>(n);
    k_scatter<<<(e + 255) / 256, 256>>>(src, dst, e);
    k_spmm<<<(n + 7) / 8, 256>>>((const float4*)x, n);
    k_gemm<<<(n + 127) / 128, 256>>>(x0, w1, w2, out, n);
}

// round 7
// speedup vs baseline: 1.9552x; 1.0147x over previous
#include <cuda_runtime.h>

#define CHN 128
#define NMAX 100000
#define EMAX 800000

static __device__ float g_deg[NMAX];                 // degree -> rsqrt(degree)
static __device__ float g_h[(size_t)NMAX * CHN];     // aggregated features
static __device__ int   g_rowptr[NMAX];              // CSR row starts
static __device__ int   g_cursor[NMAX];              // scatter cursors -> counts
static __device__ int   g_csrsrc[EMAX];              // CSR column (src) indices
static __device__ int   g_aux[128];                  // scan block sums

__device__ __forceinline__ unsigned cvt_tf32(float f) {
    unsigned r;
    asm("cvt.rna.tf32.f32 %0, %1;" : "=r"(r) : "f"(f));
    return r;
}

// ---------------------------------------------------------------------------
// Stage 1: degree histogram
// ---------------------------------------------------------------------------
__global__ void k_init(int n) {
    int i = blockIdx.x * blockDim.x + threadIdx.x;
    if (i < n) g_deg[i] = 1.0f;  // self loop
}

__global__ void k_edge_deg(const int* __restrict__ dst, int e) {
    int i = blockIdx.x * blockDim.x + threadIdx.x;
    if (i < e) atomicAdd(&g_deg[dst[i]], 1.0f);
}

// ---------------------------------------------------------------------------
// Stage 2: exclusive scan of (deg-1) -> rowptr; fused dis = rsqrt(deg)
// ---------------------------------------------------------------------------
__global__ void __launch_bounds__(1024) k_scan1(int n) {
    __shared__ int wsum[32];
    int i = blockIdx.x * 1024 + threadIdx.x;
    float dg = (i < n) ? g_deg[i] : 1.0f;
    int v = (i < n) ? ((int)dg - 1) : 0;
    if (i < n) g_deg[i] = rsqrtf(dg);
    int x = v;
#pragma unroll
    for (int o = 1; o < 32; o <<= 1) {
        int y = __shfl_up_sync(~0u, x, o);
        if ((threadIdx.x & 31) >= o) x += y;
    }
    if ((threadIdx.x & 31) == 31) wsum[threadIdx.x >> 5] = x;
    __syncthreads();
    if (threadIdx.x < 32) {
        int s = wsum[threadIdx.x];
#pragma unroll
        for (int o = 1; o < 32; o <<= 1) {
            int y = __shfl_up_sync(~0u, s, o);
            if (threadIdx.x >= o) s += y;
        }
        wsum[threadIdx.x] = s;
    }
    __syncthreads();
    int base = (threadIdx.x >= 32) ? wsum[(threadIdx.x >> 5) - 1] : 0;
    if (i < n) g_rowptr[i] = base + x - v;
    if (threadIdx.x == 1023) g_aux[blockIdx.x] = base + x;
}

__global__ void k_scan2(int nb) {   // nb <= 128; shfl scan over 128 threads
    int tid = threadIdx.x;
    int v = (tid < nb) ? g_aux[tid] : 0;
    int x = v;
#pragma unroll
    for (int o = 1; o < 32; o <<= 1) {
        int y = __shfl_up_sync(~0u, x, o);
        if ((tid & 31) >= o) x += y;
    }
    __shared__ int ws[4];
    if ((tid & 31) == 31) ws[tid >> 5] = x;
    __syncthreads();
    if (tid < 4) {
        int s = ws[tid];
        int r0 = __shfl_up_sync(0xF, s, 1); if (tid >= 1) s += r0;
        int r1 = __shfl_up_sync(0xF, s, 2); if (tid >= 2) s += r1;
        ws[tid] = s;
    }
    __syncthreads();
    int base = (tid >= 32) ? ws[(tid >> 5) - 1] : 0;
    if (tid < nb) g_aux[tid] = base + x - v;   // exclusive
}

__global__ void k_scan3(int n) {
    int i = blockIdx.x * blockDim.x + threadIdx.x;
    if (i < n) {
        g_rowptr[i] += g_aux[i >> 10];
        g_cursor[i] = 0;
    }
}

// ---------------------------------------------------------------------------
// Stage 3: scatter edges into CSR
// ---------------------------------------------------------------------------
__global__ void k_scatter(const int* __restrict__ src, const int* __restrict__ dst, int e) {
    int i = blockIdx.x * blockDim.x + threadIdx.x;
    if (i >= e) return;
    int d = dst[i];
    int pos = g_rowptr[d] + atomicAdd(&g_cursor[d], 1);
    g_csrsrc[pos] = src[i];
}

// ---------------------------------------------------------------------------
// Stage 4: CSR SpMM — one warp per dst row; gather batches of 8/4/1 (MLP=8).
// ---------------------------------------------------------------------------
__global__ void __launch_bounds__(256) k_spmm(const float4* __restrict__ x4, int n) {
    int w = (blockIdx.x * 256 + threadIdx.x) >> 5;
    int lane = threadIdx.x & 31;
    if (w >= n) return;
    float dd = g_deg[w];
    float4 acc = x4[(size_t)w * 32 + lane];
    float c = dd * dd;
    acc.x *= c; acc.y *= c; acc.z *= c; acc.w *= c;
    int beg = g_rowptr[w];
    int cnt = g_cursor[w];
    for (int c0 = 0; c0 < cnt; c0 += 32) {
        int m = min(32, cnt - c0);
        int s = 0;
        float wv = 0.f;
        if (lane < m) {
            s = g_csrsrc[beg + c0 + lane];
            wv = g_deg[s] * dd;
        }
        int j = 0;
        for (; j + 8 <= m; j += 8) {
            int si[8]; float ni[8]; float4 v[8];
#pragma unroll
            for (int q = 0; q < 8; q++) {
                si[q] = __shfl_sync(~0u, s, j + q);
                ni[q] = __shfl_sync(~0u, wv, j + q);
            }
#pragma unroll
            for (int q = 0; q < 8; q++) v[q] = x4[(size_t)si[q] * 32 + lane];
#pragma unroll
            for (int q = 0; q < 8; q++) {
                acc.x += ni[q] * v[q].x; acc.y += ni[q] * v[q].y;
                acc.z += ni[q] * v[q].z; acc.w += ni[q] * v[q].w;
            }
        }
        for (; j + 4 <= m; j += 4) {
            int si[4]; float ni[4]; float4 v[4];
#pragma unroll
            for (int q = 0; q < 4; q++) {
                si[q] = __shfl_sync(~0u, s, j + q);
                ni[q] = __shfl_sync(~0u, wv, j + q);
            }
#pragma unroll
            for (int q = 0; q < 4; q++) v[q] = x4[(size_t)si[q] * 32 + lane];
#pragma unroll
            for (int q = 0; q < 4; q++) {
                acc.x += ni[q] * v[q].x; acc.y += ni[q] * v[q].y;
                acc.z += ni[q] * v[q].z; acc.w += ni[q] * v[q].w;
            }
        }
        for (; j < m; j++) {
            int sj = __shfl_sync(~0u, s, j);
            float nr = __shfl_sync(~0u, wv, j);
            float4 v = x4[(size_t)sj * 32 + lane];
            acc.x += nr * v.x; acc.y += nr * v.y;
            acc.z += nr * v.z; acc.w += nr * v.w;
        }
    }
    reinterpret_cast<float4*>(g_h)[(size_t)w * 32 + lane] = acc;
}

// ---------------------------------------------------------------------------
// Stage 5: out = relu([h|x0] @ (beta*[W1;W2] + c1*[I;I]))  via tf32 mma.sync
// Double-buffered smem stages (dynamic, 2 x 35 KB), one sync per K-chunk:
//   loads(kc+1) -> mma(buf kc) -> stores(kc+1 -> other buf) -> sync.
// Fragment patterns conflict-free: A bank g*4+t4, B bank t4*8+g.
// ---------------------------------------------------------------------------
#define SA 36
#define SB 136
#define STAGE_WORDS (128 * SA + 32 * SB)     // 8960 words = 35840 B

__global__ void __launch_bounds__(256, 2) k_gemm(const float* __restrict__ x0,
                                                 const float* __restrict__ w1,
                                                 const float* __restrict__ w2,
                                                 float* __restrict__ out, int n) {
    extern __shared__ unsigned dynsm[];
    const float BETA = 0.6931471805599453f;
    const float C1 = 0.15342640972002733f;

    int tid = threadIdx.x, warp = tid >> 5, lane = tid & 31;
    int g = lane >> 2, t4 = lane & 3;
    int row0 = blockIdx.x * 128;

    float4 ra[4];   // A-chunk staging (128x32 / 256 thr = 4 float4)
    float4 rw[4];   // W-chunk staging (32x128 / 256 thr = 4 float4)

    auto loadA = [&](int kc) {
        const float* Asrc = (kc < 4) ? g_h : x0;
        int kbase = (kc & 3) * 32;
#pragma unroll
        for (int i = 0; i < 4; i++) {
            int t = tid + i * 256;
            int r = t >> 3, q = t & 7;
            int gr = row0 + r;
            ra[i] = (gr < n) ? *(const float4*)(Asrc + (size_t)gr * CHN + kbase + q * 4)
                             : make_float4(0.f, 0.f, 0.f, 0.f);
        }
    };
    auto loadW = [&](int kc) {
#pragma unroll
        for (int i = 0; i < 4; i++) {
            int t = tid + i * 256;
            int kk = t >> 5, q = t & 31;
            int kg = kc * 32 + kk;
            const float* Wr = (kg < 128) ? (w1 + (size_t)kg * CHN)
                                         : (w2 + (size_t)(kg - 128) * CHN);
            rw[i] = *(const float4*)(Wr + q * 4);
        }
    };
    auto storeStage = [&](int kc, unsigned* As, unsigned* Ws) {
#pragma unroll
        for (int i = 0; i < 4; i++) {
            int t = tid + i * 256;
            int r = t >> 3, q = t & 7;
            uint4 u = make_uint4(cvt_tf32(ra[i].x), cvt_tf32(ra[i].y),
                                 cvt_tf32(ra[i].z), cvt_tf32(ra[i].w));
            *reinterpret_cast<uint4*>(&As[r * SA + q * 4]) = u;
        }
#pragma unroll
        for (int i = 0; i < 4; i++) {
            int t = tid + i * 256;
            int kk = t >> 5, q = t & 31;
            int kg = kc * 32 + kk, kd = kg & 127, c = q * 4;
            uint4 u;
            u.x = cvt_tf32(BETA * rw[i].x + (kd == c + 0 ? C1 : 0.f));
            u.y = cvt_tf32(BETA * rw[i].y + (kd == c + 1 ? C1 : 0.f));
            u.z = cvt_tf32(BETA * rw[i].z + (kd == c + 2 ? C1 : 0.f));
            u.w = cvt_tf32(BETA * rw[i].w + (kd == c + 3 ? C1 : 0.f));
            *reinterpret_cast<uint4*>(&Ws[kk * SB + c]) = u;
        }
    };

    float acc[16][4];
#pragma unroll
    for (int nt = 0; nt < 16; nt++)
#pragma unroll
        for (int j = 0; j < 4; j++) acc[nt][j] = 0.f;

    loadA(0);
    loadW(0);
    storeStage(0, dynsm, dynsm + 128 * SA);
    __syncthreads();

    for (int kc = 0; kc < 8; kc++) {
        unsigned* Ac = dynsm + (kc & 1) * STAGE_WORDS;
        unsigned* Wc = Ac + 128 * SA;
        if (kc < 7) { loadA(kc + 1); loadW(kc + 1); }  // LDG overlaps mma below

#pragma unroll
        for (int k8 = 0; k8 < 4; k8++) {
            int ar = warp * 16 + g;
            int kb = k8 * 8;
            unsigned a0 = Ac[ar * SA + kb + t4];
            unsigned a1 = Ac[(ar + 8) * SA + kb + t4];
            unsigned a2 = Ac[ar * SA + kb + t4 + 4];
            unsigned a3 = Ac[(ar + 8) * SA + kb + t4 + 4];
#pragma unroll
            for (int nt = 0; nt < 16; nt++) {
                unsigned b0 = Wc[(kb + t4) * SB + nt * 8 + g];
                unsigned b1 = Wc[(kb + t4 + 4) * SB + nt * 8 + g];
                asm volatile(
                    "mma.sync.aligned.m16n8k8.row.col.f32.tf32.tf32.f32 "
                    "{%0,%1,%2,%3}, {%4,%5,%6,%7}, {%8,%9}, {%0,%1,%2,%3};"
                    : "+f"(acc[nt][0]), "+f"(acc[nt][1]),
                      "+f"(acc[nt][2]), "+f"(acc[nt][3])
                    : "r"(a0), "r"(a1), "r"(a2), "r"(a3), "r"(b0), "r"(b1));
            }
        }

        if (kc < 7) {
            unsigned* An = dynsm + ((kc + 1) & 1) * STAGE_WORDS;
            storeStage(kc + 1, An, An + 128 * SA);
            __syncthreads();
        }
    }

    int r1 = row0 + warp * 16 + g;
    int r2 = r1 + 8;
#pragma unroll
    for (int nt = 0; nt < 16; nt++) {
        int c = nt * 8 + t4 * 2;
        if (r1 < n) {
            float2 o = make_float2(fmaxf(acc[nt][0], 0.f), fmaxf(acc[nt][1], 0.f));
            *reinterpret_cast<float2*>(out + (size_t)r1 * CHN + c) = o;
        }
        if (r2 < n) {
            float2 o = make_float2(fmaxf(acc[nt][2], 0.f), fmaxf(acc[nt][3], 0.f));
            *reinterpret_cast<float2*>(out + (size_t)r2 * CHN + c) = o;
        }
    }
}

// ---------------------------------------------------------------------------
extern "C" void kernel_launch(void* const* d_in, const int* in_sizes, int n_in,
                              void* d_out, int out_size) {
    const float* x  = (const float*)d_in[0];
    const float* x0 = (const float*)d_in[1];
    const float* w1 = (const float*)d_in[2];
    const float* w2 = (const float*)d_in[3];
    const int*   ei = (const int*)d_in[4];
    float* out = (float*)d_out;

    const int n = in_sizes[0] / CHN;   // 100000
    const int e = in_sizes[4] / 2;     // 800000
    const int* src = ei;
    const int* dst = ei + e;
    const int nb = (n + 1023) / 1024;
    const int gemm_smem = 2 * STAGE_WORDS * 4;   // 71680 B

    cudaFuncSetAttribute(k_gemm, cudaFuncAttributeMaxDynamicSharedMemorySize,
                         gemm_smem);   // host-side config; runs at capture only

    k_init<<<(n + 255) / 256, 256>>>(n);
    k_edge_deg<<<(e + 255) / 256, 256>>>(dst, e);
    k_scan1<<<nb, 1024>>>(n);
    k_scan2<<<1, 128>>>(nb);
    k_scan3<<<(n + 255) / 256, 256>>>(n);
    k_scatter<<<(e + 255) / 256, 256>>>(src, dst, e);
    k_spmm<<<(n + 7) / 8, 256>>>((const float4*)x, n);
    k_gemm<<<(n + 127) / 128, 256, gemm_smem>>>(x0, w1, w2, out, n);
}